// round 2
// baseline (speedup 1.0000x reference)
#include <cuda_runtime.h>

#define CIN  512
#define COUT 256
#define BATCH 32
#define HIN  56
#define WIN  56
#define HO   28
#define WO   28
#define NPIX (HO*WO)   // 784

#define TO 128   // output-channel tile
#define TP 64    // pixel tile
#define BK 16    // k chunk
#define WSS 132  // padded Ws row stride (floats): conflict-free transposed stores, 16B-aligned reads

// Scratch: pooled BN+ReLU activations, [B, Cin, 28*28] fp32 (≈51.4 MB)
__device__ float g_hp[(size_t)BATCH * CIN * NPIX];

// ---------- f32x2 packed-FMA helpers ----------
__device__ __forceinline__ unsigned long long pack2(float x, float y) {
    unsigned long long r;
    asm("mov.b64 %0, {%1, %2};" : "=l"(r) : "f"(x), "f"(y));
    return r;
}
__device__ __forceinline__ float2 unpack2(unsigned long long v) {
    float2 r;
    asm("mov.b64 {%0, %1}, %2;" : "=f"(r.x), "=f"(r.y) : "l"(v));
    return r;
}
__device__ __forceinline__ unsigned long long fma2(unsigned long long a,
                                                   unsigned long long b,
                                                   unsigned long long c) {
    unsigned long long d;
    asm("fma.rn.f32x2 %0, %1, %2, %3;" : "=l"(d) : "l"(a), "l"(b), "l"(c));
    return d;
}

// ---------- Kernel 1: BN + ReLU + 2x2 avgpool ----------
// hp[b][c][i*28+j] = 0.25 * sum_{2x2} relu(x*scale + shift)
__global__ __launch_bounds__(256) void pool_bn_relu_kernel(
    const float* __restrict__ x,
    const float* __restrict__ bn_w, const float* __restrict__ bn_b,
    const float* __restrict__ r_mean, const float* __restrict__ r_var)
{
    int p = blockIdx.x * 256 + threadIdx.x;
    if (p >= NPIX) return;
    int c = blockIdx.y;
    int b = blockIdx.z;

    float s = bn_w[c] * rsqrtf(r_var[c] + 1e-5f);
    float t = fmaf(-r_mean[c], s, bn_b[c]);

    int i = p / WO, j = p % WO;
    const float* xp = x + (((size_t)b * CIN + c) * HIN + 2 * i) * WIN + 2 * j;
    float2 r0 = *(const float2*)xp;
    float2 r1 = *(const float2*)(xp + WIN);

    float sum = fmaxf(fmaf(r0.x, s, t), 0.0f) + fmaxf(fmaf(r0.y, s, t), 0.0f)
              + fmaxf(fmaf(r1.x, s, t), 0.0f) + fmaxf(fmaf(r1.y, s, t), 0.0f);

    g_hp[((size_t)b * CIN + c) * NPIX + p] = 0.25f * sum;
}

// ---------- Kernel 2: per-image GEMM  out[b] = W[256,512] @ hp[b][512,784] ----------
// Register-prefetch pipelined: next k-tile's LDGs issue before the FMA block,
// commit to smem after it, so DRAM/L2 latency hides under the FMA-pipe floor.
__global__ __launch_bounds__(256) void gemm_kernel(
    const float* __restrict__ wgt,   // [COUT, CIN]
    float* __restrict__ out)         // [B, COUT, 784]
{
    __shared__ float Ws[BK][WSS];    // transposed: Ws[k][o]
    __shared__ float Hs[BK][TP];     // Hs[k][p]

    const int tid = threadIdx.x;
    const int tx  = tid & 15;        // pixel group 0..15
    const int ty  = tid >> 4;        // o-row group 0..15
    const int p0  = blockIdx.x * TP;
    const int o0  = blockIdx.y * TO;
    const int b   = blockIdx.z;

    // global->shared load indexing
    const int wrow = tid >> 2;           // 0..63
    const int wcol = (tid & 3) * 4;      // 0,4,8,12
    const int hrow = tid >> 4;           // 0..15
    const int hcol = (tid & 15) * 4;     // 0..60
    const bool hvalid = (p0 + hcol) < NPIX;   // float4 fully in-range (784 % 4 == 0)

    // streaming pointers (k0 advances by BK each iter)
    const float* wp0 = &wgt[(size_t)(o0 + wrow) * CIN + wcol];        // pass 0
    const float* wp1 = &wgt[(size_t)(o0 + 64 + wrow) * CIN + wcol];   // pass 1
    const float* hpp = g_hp + (size_t)b * CIN * NPIX + (size_t)hrow * NPIX + p0 + hcol;

    unsigned long long acc[4][4];
    #pragma unroll
    for (int r = 0; r < 4; r++)
        #pragma unroll
        for (int c = 0; c < 4; c++) acc[r][c] = 0ull;

    // ---- prologue: load k-tile 0 into registers ----
    float4 wv0 = *(const float4*)wp0;
    float4 wv1 = *(const float4*)wp1;
    float4 hv  = hvalid ? *(const float4*)hpp : make_float4(0.f, 0.f, 0.f, 0.f);

    for (int k0 = 0; k0 < CIN; k0 += BK) {
        // commit prefetched tile to smem
        Ws[wcol + 0][wrow]      = wv0.x;
        Ws[wcol + 1][wrow]      = wv0.y;
        Ws[wcol + 2][wrow]      = wv0.z;
        Ws[wcol + 3][wrow]      = wv0.w;
        Ws[wcol + 0][64 + wrow] = wv1.x;
        Ws[wcol + 1][64 + wrow] = wv1.y;
        Ws[wcol + 2][64 + wrow] = wv1.z;
        Ws[wcol + 3][64 + wrow] = wv1.w;
        *(float4*)&Hs[hrow][hcol] = hv;

        __syncthreads();

        // issue next tile's global loads (latency hides under FMA block)
        if (k0 + BK < CIN) {
            wp0 += BK; wp1 += BK; hpp += (size_t)BK * NPIX;
            wv0 = *(const float4*)wp0;
            wv1 = *(const float4*)wp1;
            if (hvalid) hv = *(const float4*)hpp;
        }

        #pragma unroll
        for (int kk = 0; kk < BK; kk++) {
            // a: 8 consecutive o values => 4 pre-packed f32x2 pairs
            ulonglong2 a01 = *(const ulonglong2*)&Ws[kk][ty * 8];
            ulonglong2 a23 = *(const ulonglong2*)&Ws[kk][ty * 8 + 4];
            // b: 4 pixel values, duplicated into both lanes
            float4 bf = *(const float4*)&Hs[kk][tx * 4];
            unsigned long long bd0 = pack2(bf.x, bf.x);
            unsigned long long bd1 = pack2(bf.y, bf.y);
            unsigned long long bd2 = pack2(bf.z, bf.z);
            unsigned long long bd3 = pack2(bf.w, bf.w);

            acc[0][0] = fma2(a01.x, bd0, acc[0][0]);
            acc[0][1] = fma2(a01.x, bd1, acc[0][1]);
            acc[0][2] = fma2(a01.x, bd2, acc[0][2]);
            acc[0][3] = fma2(a01.x, bd3, acc[0][3]);
            acc[1][0] = fma2(a01.y, bd0, acc[1][0]);
            acc[1][1] = fma2(a01.y, bd1, acc[1][1]);
            acc[1][2] = fma2(a01.y, bd2, acc[1][2]);
            acc[1][3] = fma2(a01.y, bd3, acc[1][3]);
            acc[2][0] = fma2(a23.x, bd0, acc[2][0]);
            acc[2][1] = fma2(a23.x, bd1, acc[2][1]);
            acc[2][2] = fma2(a23.x, bd2, acc[2][2]);
            acc[2][3] = fma2(a23.x, bd3, acc[2][3]);
            acc[3][0] = fma2(a23.y, bd0, acc[3][0]);
            acc[3][1] = fma2(a23.y, bd1, acc[3][1]);
            acc[3][2] = fma2(a23.y, bd2, acc[3][2]);
            acc[3][3] = fma2(a23.y, bd3, acc[3][3]);
        }
        __syncthreads();
    }

    // store 8 rows x 4 cols per thread
    if ((p0 + tx * 4) < NPIX) {
        float* ob = out + ((size_t)b * COUT + o0 + ty * 8) * NPIX + p0 + tx * 4;
        #pragma unroll
        for (int rp = 0; rp < 4; rp++) {
            float2 c0 = unpack2(acc[rp][0]);
            float2 c1 = unpack2(acc[rp][1]);
            float2 c2 = unpack2(acc[rp][2]);
            float2 c3 = unpack2(acc[rp][3]);
            *(float4*)(ob + (size_t)(2 * rp) * NPIX)     = make_float4(c0.x, c1.x, c2.x, c3.x);
            *(float4*)(ob + (size_t)(2 * rp + 1) * NPIX) = make_float4(c0.y, c1.y, c2.y, c3.y);
        }
    }
}

extern "C" void kernel_launch(void* const* d_in, const int* in_sizes, int n_in,
                              void* d_out, int out_size)
{
    const float* x    = (const float*)d_in[0];
    const float* bn_w = (const float*)d_in[1];
    const float* bn_b = (const float*)d_in[2];
    const float* rm   = (const float*)d_in[3];
    const float* rv   = (const float*)d_in[4];
    const float* wgt  = (const float*)d_in[5];
    float* out        = (float*)d_out;

    dim3 g1((NPIX + 255) / 256, CIN, BATCH);          // (4, 512, 32)
    pool_bn_relu_kernel<<<g1, 256>>>(x, bn_w, bn_b, rm, rv);

    dim3 g2((NPIX + TP - 1) / TP, COUT / TO, BATCH);  // (13, 2, 32)
    gemm_kernel<<<g2, 256>>>(wgt, out);
}